// round 2
// baseline (speedup 1.0000x reference)
#include <cuda_runtime.h>
#include <cuda_bf16.h>

#define NA 4096
#define H  64
#define OD 48
#define NSEG 48
#define PC (NSEG * OD)   /* 2304 */

// Scratch (device globals: allocation-free rule)
__device__ float g_P[(size_t)NA * PC];   // 37.7 MB, L2-resident during k_main
__device__ float g_Wt[H * PC];           // 589 KB reshaped weights

// ---------------------------------------------------------------------------
// Wt[k][s*48+o] = fc_w[o, s*64+k]
// ---------------------------------------------------------------------------
__global__ void k_reshape(const float* __restrict__ fw) {
    int idx = blockIdx.x * blockDim.x + threadIdx.x;
    if (idx >= H * PC) return;
    int k = idx / PC, c = idx - k * PC;
    int s = c / OD, o = c - s * OD;
    g_Wt[idx] = fw[o * (NSEG * H) + s * H + k];
}

// ---------------------------------------------------------------------------
// P[j][c] = sum_k hidden[j][k] * Wt[k][c]   (block: 8 j-rows x 2304 cols)
// ---------------------------------------------------------------------------
__global__ __launch_bounds__(256) void k_gemmP(const float* __restrict__ hidden) {
    __shared__ float sh[8][H];
    int t = threadIdx.x;
    int jb = blockIdx.x * 8;
    for (int idx = t; idx < 8 * H; idx += 256)
        sh[idx >> 6][idx & 63] = hidden[jb * H + idx];
    __syncthreads();

    float acc[8][9];
#pragma unroll
    for (int j = 0; j < 8; j++)
#pragma unroll
        for (int u = 0; u < 9; u++) acc[j][u] = 0.f;

    for (int k = 0; k < H; k++) {
        float w[9];
#pragma unroll
        for (int u = 0; u < 9; u++) w[u] = g_Wt[k * PC + u * 256 + t];
#pragma unroll
        for (int j = 0; j < 8; j++) {
            float hv = sh[j][k];
#pragma unroll
            for (int u = 0; u < 9; u++) acc[j][u] = fmaf(hv, w[u], acc[j][u]);
        }
    }
#pragma unroll
    for (int j = 0; j < 8; j++)
#pragma unroll
        for (int u = 0; u < 9; u++)
            g_P[(size_t)(jb + j) * PC + u * 256 + t] = acc[j][u];
}

// ---------------------------------------------------------------------------
// seg(i,j): MUFU-free. ring via r^2 thresholds (0.25*8^(2t/5)); wedge via
// octant comparisons replicating trunc(atan2(dy,dx)*4/pi + 3) mod 8.
// Returns 48 when invalid (r<RMIN, ring>=6, or j==i giving r=0).
// ---------------------------------------------------------------------------
__device__ __forceinline__ int seg_of(float xi, float yi, float xj, float yj) {
    float dx = xj - xi, dy = yj - yi;     // j - i (matches reference theta)
    float r2 = fmaf(dx, dx, dy * dy);
    if (r2 < 0.25f)          return NSEG;   // r < RMIN  -> ring = -1
    if (r2 >= 36.75834735f)  return NSEG;   // ring >= 6
    int ring = (r2 >= 0.574349177f) + (r2 >= 1.319507911f) + (r2 >= 3.031433132f)
             + (r2 >= 6.964404507f) + (r2 >= 16.0f);
    int w;
    if (dy > 0.f) {
        if (dx > 0.f)      w = (dy <  dx) ? 3 : 4;   // theta in (0, pi/2)
        else if (dx < 0.f) w = (dy > -dx) ? 5 : 6;   // theta in (pi/2, pi)
        else               w = 5;                    // theta = pi/2
    } else if (dy < 0.f) {
        if (dx > 0.f)      w = (-dy <= dx) ? 2 : 1;  // theta in (-pi/2, 0)
        else if (dx < 0.f) w = 0;                    // theta in (-pi, -pi/2)
        else               w = 1;                    // theta = -pi/2
    } else {
        w = (dx >= 0.f) ? 3 : 7;                     // theta = 0 or pi
    }
    return ring * 8 + w;
}

// ---------------------------------------------------------------------------
// Main: one warp per agent i.
// Sweep 1: counts via lane-private smem u16 histograms (no atomics).
// Sweep 2: out[i,o] += invc[s_ij] * P[j, s_ij, o]; lane l owns outs {2l,2l+1}.
// ---------------------------------------------------------------------------
__global__ __launch_bounds__(256) void k_main(const float2* __restrict__ yp,
                                              const float* __restrict__ fb,
                                              float* __restrict__ out) {
    __shared__ unsigned short hist[8][48 * 33];  // [warp][s*33 + lane], padded
    __shared__ float invc[8][48];
    int wp = threadIdx.x >> 5, lane = threadIdx.x & 31;
    int i = blockIdx.x * 8 + wp;
    float2 pi = yp[i];

    for (int idx = lane; idx < 48 * 33; idx += 32) hist[wp][idx] = 0;
    __syncwarp();

    // ---- sweep 1: per-segment counts ----
    for (int base = 0; base < NA; base += 32) {
        float2 pj = yp[base + lane];
        int s = seg_of(pi.x, pi.y, pj.x, pj.y);
        if (s < NSEG) hist[wp][s * 33 + lane]++;   // max per-lane count = 128, fits u16
    }
    __syncwarp();
    for (int s = lane; s < NSEG; s += 32) {
        int c = 0;
#pragma unroll
        for (int k = 0; k < 32; k++) c += hist[wp][s * 33 + k];
        invc[wp][s] = (c > 0) ? (1.0f / (float)c) : 0.0f;
    }
    __syncwarp();

    // ---- sweep 2: gather-FMA over P ----
    float ax = 0.f, ay = 0.f;
    bool act = lane < 24;                 // 24 lanes x float2 = 48 outputs
    for (int base = 0; base < NA; base += 32) {
        float2 pj = yp[base + lane];
        int s = seg_of(pi.x, pi.y, pj.x, pj.y);
        const float* rowbase = g_P + (size_t)base * PC;
#pragma unroll
        for (int k = 0; k < 32; k++) {
            int sk = __shfl_sync(0xffffffffu, s, k);
            if (sk < NSEG) {                       // uniform branch
                float wv = invc[wp][sk];           // broadcast LDS
                if (act) {
                    const float2* p =
                        (const float2*)(rowbase + k * PC + sk * OD);
                    float2 v = p[lane];            // coalesced 192B gather
                    ax = fmaf(wv, v.x, ax);
                    ay = fmaf(wv, v.y, ay);
                }
            }
        }
    }

    if (act) {
        float r0 = ax + fb[2 * lane];
        float r1 = ay + fb[2 * lane + 1];
        float2 res = make_float2(fmaxf(r0, 0.f), fmaxf(r1, 0.f));
        *(float2*)(out + i * OD + 2 * lane) = res;
    }
}

// ---------------------------------------------------------------------------
extern "C" void kernel_launch(void* const* d_in, const int* in_sizes, int n_in,
                              void* d_out, int out_size) {
    const float* ypred  = (const float*)d_in[0];
    const float* hidden = (const float*)d_in[1];
    const float* fc_w   = (const float*)d_in[2];
    const float* fc_b   = (const float*)d_in[3];
    float* out = (float*)d_out;

    k_reshape<<<(H * PC + 255) / 256, 256>>>(fc_w);
    k_gemmP<<<NA / 8, 256>>>(hidden);
    k_main<<<NA / 8, 256>>>((const float2*)ypred, fc_b, out);
}